// round 9
// baseline (speedup 1.0000x reference)
#include <cuda_runtime.h>
#include <math.h>

#define NPIX (512*512)
#define NB 16
#define SIG 0.125f
#define TAUC 0.125f
#define ALPHA_C 0.15f
#define MU_C 10.0f
#define EPS_C 1e-6f
#define INV1T (1.0f/1.125f)
#define FRLO 0.43000000000029104f
#define FRHI 0.5699999999953434f

// fused PD tiling (shuffle version)
#define TT 44
#define KK 10
#define SS 64
#define PPT 8
#define NTILE 12            // ceil(512/44)

// ---------------- device scratch ----------------
__device__ float g_tmpR[NB*NPIX];
__device__ float g_tmpM[NB*NPIX];
__device__ float g_x  [NB*NPIX];
__device__ float g_Nh [NB*NPIX];
__device__ float g_gm [NB*NPIX];
__device__ float g_Wx [NB*NPIX];   // ALPHA*Wx
__device__ float g_Wy [NB*NPIX];   // ALPHA*Wy
__device__ float g_u [2][NB*NPIX];
__device__ float g_ub[2][NB*NPIX];
__device__ float g_px[2][NB*NPIX];
__device__ float g_py[2][NB*NPIX];

// radix 8 + 12 + 12
__device__ unsigned g_hist1 [NB*256];        // x pass-1 (8 bits)
__device__ unsigned g_hist1g[NB*256];        // gm pass-1
__device__ unsigned g_histX2[NB*4*4096];     // x pass-2 (12 bits)
__device__ unsigned g_histX3[NB*4*4096];     // x pass-3 (12 bits)
__device__ unsigned g_histG2[NB*2*4096];
__device__ unsigned g_histG3[NB*2*4096];

__constant__ int c_ranksX[4] = {2621, 2622, 259521, 259522};
__constant__ int c_ranksG[2] = {131071, 131072};

// ---------------- zero all histogram buffers ----------------
__global__ void k_zero_hists() {
    int stride = gridDim.x * blockDim.x;
    int i0 = blockIdx.x * blockDim.x + threadIdx.x;
    for (int i = i0; i < NB*256; i += stride) { g_hist1[i] = 0; g_hist1g[i] = 0; }
    for (int i = i0; i < NB*4*4096; i += stride) { g_histX2[i] = 0; g_histX3[i] = 0; }
    for (int i = i0; i < NB*2*4096; i += stride) { g_histG2[i] = 0; g_histG3[i] = 0; }
}

// ---------------- warp-collective resolve steps ----------------
// 256-bin: counts cached in 8 regs/lane
__device__ __forceinline__ unsigned wrs256(const unsigned* hist, unsigned& rank, int lane) {
    unsigned c[8]; unsigned s = 0;
    #pragma unroll
    for (int i = 0; i < 8; i++) { c[i] = __ldg(&hist[lane*8 + i]); s += c[i]; }
    unsigned pre = s;
    #pragma unroll
    for (int d = 1; d < 32; d <<= 1) {
        unsigned v = __shfl_up_sync(0xffffffffu, pre, d);
        if (lane >= d) pre += v;
    }
    unsigned excl = pre - s;
    bool hit = (rank >= excl) && (rank < excl + s);
    unsigned m = __ballot_sync(0xffffffffu, hit);
    if (!m) { rank = 0; return 255u; }
    int hl = __ffs(m) - 1;
    unsigned bkt = 0, rr = 0;
    if (lane == hl) {
        rr = rank - excl;
        int i = 0;
        while (i < 7 && rr >= c[i]) { rr -= c[i]; i++; }
        bkt = (unsigned)(hl*8 + i);
    }
    bkt = __shfl_sync(0xffffffffu, bkt, hl);
    rr  = __shfl_sync(0xffffffffu, rr,  hl);
    rank = rr;
    return bkt;
}

// 4096-bin: two-level (stream-sum 128/lane, then 4/lane within hit range)
__device__ __forceinline__ unsigned wrs4096(const unsigned* hist, unsigned& rank, int lane) {
    const unsigned FULL = 0xffffffffu;
    unsigned s = 0;
    #pragma unroll 8
    for (int i = 0; i < 128; i++) s += __ldg(&hist[lane*128 + i]);
    unsigned pre = s;
    #pragma unroll
    for (int d = 1; d < 32; d <<= 1) {
        unsigned v = __shfl_up_sync(FULL, pre, d);
        if (lane >= d) pre += v;
    }
    unsigned excl = pre - s;
    bool hit = (rank >= excl) && (rank < excl + s);
    unsigned m = __ballot_sync(FULL, hit);
    if (!m) { rank = 0; return 4095u; }
    int hl = __ffs(m) - 1;
    unsigned rr = __shfl_sync(FULL, rank - excl, hl);
    // level 2 within hl's 128 bins
    const unsigned* h2 = hist + hl*128;
    unsigned c4[4]; unsigned s2 = 0;
    #pragma unroll
    for (int i = 0; i < 4; i++) { c4[i] = __ldg(&h2[lane*4 + i]); s2 += c4[i]; }
    unsigned pre2 = s2;
    #pragma unroll
    for (int d = 1; d < 32; d <<= 1) {
        unsigned v = __shfl_up_sync(FULL, pre2, d);
        if (lane >= d) pre2 += v;
    }
    unsigned excl2 = pre2 - s2;
    bool hit2 = (rr >= excl2) && (rr < excl2 + s2);
    unsigned m2 = __ballot_sync(FULL, hit2);
    int hl2 = m2 ? (__ffs(m2) - 1) : 31;
    unsigned bkt = 0, rrr = 0;
    if (lane == hl2) {
        rrr = rr - excl2;
        int i = 0;
        while (i < 3 && rrr >= c4[i]) { rrr -= c4[i]; i++; }
        bkt = (unsigned)(hl*128 + hl2*4 + i);
    }
    bkt = __shfl_sync(FULL, bkt, hl2);
    rrr = __shfl_sync(FULL, rrr, hl2);
    rank = rrr;
    return bkt;
}

// Chain passes 1..upto (1=8bit, 2=+12bit, 3=+12bit). Returns 32-bit prefix.
__device__ __forceinline__ unsigned chain_prefix(int which, int b, int tgt, int upto, int lane) {
    unsigned rank = which ? (unsigned)c_ranksG[tgt] : (unsigned)c_ranksX[tgt];
    int perB = which ? 2 : 4;
    const unsigned* h1 = (which ? g_hist1g : g_hist1) + b*256;
    unsigned prefix = wrs256(h1, rank, lane) << 24;
    if (upto >= 2) {
        const unsigned* h2 = (which ? g_histG2 : g_histX2) + (size_t)(b*perB + tgt)*4096;
        prefix |= wrs4096(h2, rank, lane) << 12;
    }
    if (upto >= 3) {
        const unsigned* h3 = (which ? g_histG3 : g_histX3) + (size_t)(b*perB + tgt)*4096;
        prefix |= wrs4096(h3, rank, lane);
    }
    return prefix;
}

// ---------------- horizontal 31-max-pool ----------------
__global__ void k_hpool(const float* __restrict__ Iy) {
    int row = blockIdx.x, b = blockIdx.y;
    __shared__ float sR[512];
    __shared__ float sM[512];
    int j = threadIdx.x;
    const float* base = Iy + (size_t)b*3*NPIX + (size_t)row*512;
    float r = __ldg(base + j);
    float m = fmaxf(__ldg(base + NPIX + j), __ldg(base + 2*NPIX + j));
    sR[j] = r; sM[j] = m;
    __syncthreads();
    float mr = r, mm = m;
    #pragma unroll
    for (int t = -15; t <= 15; t++) {
        int jj = j + t; jj = jj < 0 ? 0 : (jj > 511 ? 511 : jj);
        mr = fmaxf(mr, sR[jj]);
        mm = fmaxf(mm, sM[jj]);
    }
    size_t o = (size_t)b*NPIX + (size_t)row*512 + j;
    g_tmpR[o] = mr; g_tmpM[o] = mm;
}

// ---------------- vertical 31-max-pool + x + x pass-1 histogram ----------------
__global__ void k_vpool_x(const float* __restrict__ Iy) {
    int b = blockIdx.z;
    int col0 = blockIdx.x * 32;
    int row0 = blockIdx.y * 64;
    __shared__ float sR[94][32];
    __shared__ float sM[94][32];
    __shared__ unsigned h[8*256];
    int tid = threadIdx.y * 32 + threadIdx.x;
    for (int i = tid; i < 8*256; i += 256) h[i] = 0;
    for (int idx = tid; idx < 94*32; idx += 256) {
        int rr = idx >> 5, cc = idx & 31;
        int gr = row0 + rr - 15; gr = gr < 0 ? 0 : (gr > 511 ? 511 : gr);
        size_t o = (size_t)b*NPIX + (size_t)gr*512 + col0 + cc;
        sR[rr][cc] = g_tmpR[o];
        sM[rr][cc] = g_tmpM[o];
    }
    __syncthreads();
    int tx = threadIdx.x;
    unsigned rep = (tid & 7) * 256;
    for (int k = 0; k < 8; k++) {
        int r = threadIdx.y * 8 + k;
        float mr = -1e30f, mm = -1e30f;
        #pragma unroll
        for (int t = 0; t < 31; t++) {
            mr = fmaxf(mr, sR[r+t][tx]);
            mm = fmaxf(mm, sM[r+t][tx]);
        }
        int gr = row0 + r;
        size_t o = (size_t)b*NPIX + (size_t)gr*512 + col0 + tx;
        float R = __ldg(Iy + (size_t)b*3*NPIX + (size_t)gr*512 + col0 + tx);
        float xv = fabsf(mr - mm) + R;
        g_x[o] = xv;
        atomicAdd(&h[rep + (__float_as_uint(xv) >> 24)], 1u);
    }
    __syncthreads();
    for (int i = tid; i < 256; i += 256) {
        unsigned s = 0;
        #pragma unroll
        for (int r = 0; r < 8; r++) s += h[r*256 + i];
        if (s) atomicAdd(&g_hist1[b*256 + i], s);
    }
}

// ---------------- pass-2 conditional histogram (12 bits, 4096 bins) ----------------
__global__ void k_hist2(int which) {
    int b = blockIdx.y;
    const int perB = which ? 2 : 4;
    const float* src = which ? g_gm : g_x;
    unsigned* gh = which ? g_histG2 : g_histX2;
    extern __shared__ unsigned uh[];          // perB*4096
    __shared__ unsigned s_pref[4];
    __shared__ int s_slot[4];
    __shared__ int s_nu;
    int warp = threadIdx.x >> 5, lane = threadIdx.x & 31;
    for (int i = threadIdx.x; i < perB*4096; i += blockDim.x) uh[i] = 0;
    if (warp < perB) {
        unsigned p = chain_prefix(which, b, warp, 1, lane);
        if (lane == 0) s_pref[warp] = p >> 24;     // 8-bit key
    }
    __syncthreads();
    if (threadIdx.x == 0) {
        unsigned up[4]; int nu = 0;
        for (int j = 0; j < perB; j++) {
            int k = 0;
            while (k < nu && up[k] != s_pref[j]) k++;
            if (k == nu) up[nu++] = s_pref[j];
            s_slot[j] = k;
        }
        for (int k = 0; k < nu; k++) s_pref[k] = up[k];
        s_nu = nu;
    }
    __syncthreads();
    int nu = s_nu;
    unsigned p0 = s_pref[0];
    unsigned p1 = (nu > 1) ? s_pref[1] : 0xFFFFFFFFu;
    unsigned p2 = (nu > 2) ? s_pref[2] : 0xFFFFFFFFu;
    unsigned p3 = (nu > 3) ? s_pref[3] : 0xFFFFFFFFu;

    const float4* p = (const float4*)(src + (size_t)b*NPIX);
    for (int i = blockIdx.x * blockDim.x + threadIdx.x; i < NPIX/4; i += gridDim.x * blockDim.x) {
        float4 vv = __ldg(p + i);
        unsigned vs[4] = {__float_as_uint(vv.x), __float_as_uint(vv.y),
                          __float_as_uint(vv.z), __float_as_uint(vv.w)};
        #pragma unroll
        for (int e = 0; e < 4; e++) {
            unsigned v = vs[e];
            unsigned top = v >> 24;
            unsigned bin = (v >> 12) & 0xFFFu;
            if      (top == p0) atomicAdd(&uh[bin], 1u);
            else if (top == p1) atomicAdd(&uh[4096 + bin], 1u);
            else if (top == p2) atomicAdd(&uh[2*4096 + bin], 1u);
            else if (top == p3) atomicAdd(&uh[3*4096 + bin], 1u);
        }
    }
    __syncthreads();
    for (int i = threadIdx.x; i < perB*4096; i += blockDim.x) {
        int tgt = i >> 12, bin = i & 4095;
        unsigned s = uh[s_slot[tgt]*4096 + bin];
        if (s) atomicAdd(&gh[(size_t)(b*perB + tgt)*4096 + bin], s);
    }
}

// ---------------- pass-3 conditional histogram (final 12 bits) ----------------
__global__ void k_hist3(int which) {
    int b = blockIdx.y;
    const int perB = which ? 2 : 4;
    const float* src = which ? g_gm : g_x;
    unsigned* gh = which ? g_histG3 : g_histX3;
    extern __shared__ unsigned uh[];          // perB*4096
    __shared__ unsigned s_pref[4];
    __shared__ int s_slot[4];
    __shared__ int s_nu;
    int warp = threadIdx.x >> 5, lane = threadIdx.x & 31;
    for (int i = threadIdx.x; i < perB*4096; i += blockDim.x) uh[i] = 0;
    if (warp < perB) {
        unsigned p = chain_prefix(which, b, warp, 2, lane);
        if (lane == 0) s_pref[warp] = p >> 12;     // 20-bit key
    }
    __syncthreads();
    if (threadIdx.x == 0) {
        unsigned up[4]; int nu = 0;
        for (int j = 0; j < perB; j++) {
            int k = 0;
            while (k < nu && up[k] != s_pref[j]) k++;
            if (k == nu) up[nu++] = s_pref[j];
            s_slot[j] = k;
        }
        for (int k = 0; k < nu; k++) s_pref[k] = up[k];
        s_nu = nu;
    }
    __syncthreads();
    int nu = s_nu;
    unsigned p0 = s_pref[0];
    unsigned p1 = (nu > 1) ? s_pref[1] : 0xFFFFFFFFu;
    unsigned p2 = (nu > 2) ? s_pref[2] : 0xFFFFFFFFu;
    unsigned p3 = (nu > 3) ? s_pref[3] : 0xFFFFFFFFu;

    const float4* p = (const float4*)(src + (size_t)b*NPIX);
    for (int i = blockIdx.x * blockDim.x + threadIdx.x; i < NPIX/4; i += gridDim.x * blockDim.x) {
        float4 vv = __ldg(p + i);
        unsigned vs[4] = {__float_as_uint(vv.x), __float_as_uint(vv.y),
                          __float_as_uint(vv.z), __float_as_uint(vv.w)};
        #pragma unroll
        for (int e = 0; e < 4; e++) {
            unsigned v = vs[e];
            unsigned top = v >> 12;
            unsigned bin = v & 0xFFFu;
            if      (top == p0) atomicAdd(&uh[bin], 1u);
            else if (top == p1) atomicAdd(&uh[4096 + bin], 1u);
            else if (top == p2) atomicAdd(&uh[2*4096 + bin], 1u);
            else if (top == p3) atomicAdd(&uh[3*4096 + bin], 1u);
        }
    }
    __syncthreads();
    for (int i = threadIdx.x; i < perB*4096; i += blockDim.x) {
        int tgt = i >> 12, bin = i & 4095;
        unsigned s = uh[s_slot[tgt]*4096 + bin];
        if (s) atomicAdd(&gh[(size_t)(b*perB + tgt)*4096 + bin], s);
    }
}

// ---------------- N_hat + grad mag + gm pass-1 histogram; x-resolve prologue ----------------
__global__ void k_nhat() {
    int b = blockIdx.y;
    __shared__ unsigned h[8*256];
    __shared__ float s_sel[4];
    int warp = threadIdx.x >> 5, lane = threadIdx.x & 31;
    for (int i = threadIdx.x; i < 8*256; i += blockDim.x) h[i] = 0;
    if (warp < 4) {
        unsigned p = chain_prefix(0, b, warp, 3, lane);
        if (lane == 0) s_sel[warp] = __uint_as_float(p);
    }
    __syncthreads();
    float lo = s_sel[0]*(1.0f-FRLO) + s_sel[1]*FRLO;
    float hi = s_sel[2]*(1.0f-FRHI) + s_sel[3]*FRHI;
    float inv = 1.0f / (hi - lo + EPS_C);

    unsigned rep = (threadIdx.x & 7) * 256;
    size_t base = (size_t)b*NPIX;
    for (int idx = blockIdx.x * blockDim.x + threadIdx.x; idx < NPIX; idx += 64*256) {
        int i = idx >> 9, j = idx & 511;
        size_t o = base + idx;
        float xc = __ldg(&g_x[o]);
        float n00 = fminf(fmaxf((xc - lo) * inv, 0.0f), 1.0f);
        float dx = 0.0f, dy = 0.0f;
        if (j < 511) {
            float xr = __ldg(&g_x[o + 1]);
            dx = fminf(fmaxf((xr - lo) * inv, 0.0f), 1.0f) - n00;
        }
        if (i < 511) {
            float xd = __ldg(&g_x[o + 512]);
            dy = fminf(fmaxf((xd - lo) * inv, 0.0f), 1.0f) - n00;
        }
        float gm = sqrtf(dx*dx + dy*dy + EPS_C);
        g_Nh[o] = n00;
        g_gm[o] = gm;
        atomicAdd(&h[rep + (__float_as_uint(gm) >> 24)], 1u);
    }
    __syncthreads();
    for (int i = threadIdx.x; i < 256; i += blockDim.x) {
        unsigned s = 0;
        #pragma unroll
        for (int r = 0; r < 8; r++) s += h[r*256 + i];
        if (s) atomicAdd(&g_hist1g[b*256 + i], s);
    }
}

// ---------------- bounds; gm-resolve prologue ----------------
__global__ void k_wxy() {
    int b = blockIdx.y;
    __shared__ float s_sel[2];
    int warp = threadIdx.x >> 5, lane = threadIdx.x & 31;
    if (warp < 2) {
        unsigned p = chain_prefix(1, b, warp, 3, lane);
        if (lane == 0) s_sel[warp] = __uint_as_float(p);
    }
    __syncthreads();
    float med = 0.5f * (s_sel[0] + s_sel[1]);
    float isig = 1.0f / fmaxf(med, EPS_C);

    size_t base = (size_t)b*NPIX;
    for (int idx = blockIdx.x * blockDim.x + threadIdx.x; idx < NPIX; idx += 64*256) {
        int i = idx >> 9, j = idx & 511;
        size_t o = base + idx;
        float n00 = __ldg(&g_Nh[o]);
        float dx = (j < 511) ? (__ldg(&g_Nh[o + 1]) - n00) : 0.0f;
        float dy = (i < 511) ? (__ldg(&g_Nh[o + 512]) - n00) : 0.0f;
        g_Wx[o] = ALPHA_C * (1.0f + MU_C * __expf(-fabsf(dx) * isig));
        g_Wy[o] = ALPHA_C * (1.0f + MU_C * __expf(-fabsf(dy) * isig));
    }
}

// ---------------- shuffle-register fused PD ----------------
template<bool FIRST, bool LAST>
__global__ void __launch_bounds__(512, 2) k_pdshfl(int rd, int wr, float* __restrict__ out) {
    extern __shared__ float sm[];
    float* s_bx     = sm;
    float* s_by     = sm + SS*SS;
    float* s_tnh    = sm + 2*SS*SS;
    float* s_rowub  = sm + 3*SS*SS;          // [9][SS]
    float* s_rowpy  = s_rowub + 9*SS;        // [9][SS]
    float* s_seamub = s_rowpy + 9*SS;        // [SS]
    float* s_seampx = s_seamub + SS;         // [SS]

    int b = blockIdx.z;
    int rx0 = blockIdx.x * TT - KK;
    int ry0 = blockIdx.y * TT - KK;
    size_t base = (size_t)b * NPIX;
    int tx = threadIdx.x, ty = threadIdx.y;
    int R0 = ty * PPT;
    int gj = rx0 + tx;
    int gi0 = ry0 + R0;
    bool jok = (gj >= 0) && (gj < 512);

    float ru[PPT], rub[PPT], rpx[PPT], rpy[PPT];

    #pragma unroll
    for (int k = 0; k < PPT; k++) {
        int gi = gi0 + k;
        int o = (R0 + k)*SS + tx;
        if (jok && gi >= 0 && gi < 512) {
            size_t go = base + (size_t)gi*512 + gj;
            float nh = __ldg(&g_Nh[go]);
            s_tnh[o] = TAUC * nh;
            s_bx[o]  = __ldg(&g_Wx[go]);
            s_by[o]  = __ldg(&g_Wy[go]);
            if (FIRST) {
                ru[k] = nh; rub[k] = nh; rpx[k] = 0.0f; rpy[k] = 0.0f;
            } else {
                ru[k]  = __ldg(&g_u [rd][go]);
                rub[k] = __ldg(&g_ub[rd][go]);
                rpx[k] = __ldg(&g_px[rd][go]);
                rpy[k] = __ldg(&g_py[rd][go]);
            }
        } else {
            s_tnh[o] = 0.0f; s_bx[o] = 0.0f; s_by[o] = 0.0f;
            ru[k] = 0.0f; rub[k] = 0.0f; rpx[k] = 0.0f; rpy[k] = 0.0f;
        }
    }
    s_rowub[ty*SS + tx] = rub[0];
    if (ty == 0) { s_rowub[8*SS + tx] = 0.0f; s_rowpy[0*SS + tx] = 0.0f; }
    if (tx == 32) {
        #pragma unroll
        for (int k = 0; k < PPT; k++) s_seamub[R0 + k] = rub[k];
    }
    __syncthreads();

    const unsigned FULL = 0xffffffffu;
    bool jlt511 = (gj < 511);
    bool jgt0   = (gj > 0);

    for (int t = 0; t < KK; t++) {
        float ubbelow = s_rowub[(ty+1)*SS + tx];
        #pragma unroll
        for (int k = 0; k < PPT; k++) {
            float ubc = rub[k];
            float ubr = __shfl_down_sync(FULL, ubc, 1);
            if (tx == 31) ubr = s_seamub[R0 + k];
            float ubd = (k < PPT-1) ? rub[k+1] : ubbelow;
            int gi = gi0 + k;
            float dx = jlt511     ? (ubr - ubc) : 0.0f;
            float dy = (gi < 511) ? (ubd - ubc) : 0.0f;
            int o = (R0 + k)*SS + tx;
            float bx = s_bx[o], by = s_by[o];
            rpx[k] = fminf(fmaxf(rpx[k] + SIG*dx, -bx), bx);
            rpy[k] = fminf(fmaxf(rpy[k] + SIG*dy, -by), by);
        }
        s_rowpy[(ty+1)*SS + tx] = rpy[PPT-1];
        if (tx == 31) {
            #pragma unroll
            for (int k = 0; k < PPT; k++) s_seampx[R0 + k] = rpx[k];
        }
        __syncthreads();

        float pyabove = s_rowpy[ty*SS + tx];
        #pragma unroll
        for (int k = 0; k < PPT; k++) {
            float pxc = rpx[k];
            float pxl = __shfl_up_sync(FULL, pxc, 1);
            if (tx == 32) pxl = s_seampx[R0 + k];
            if (!jgt0) pxl = 0.0f;
            float pyu = (k > 0) ? rpy[k-1] : pyabove;
            int gi = gi0 + k;
            if (gi <= 0) pyu = 0.0f;
            int o = (R0 + k)*SS + tx;
            float uc = ru[k];
            float un = (uc + TAUC*(rpx[k] - pxl + rpy[k] - pyu) + s_tnh[o]) * INV1T;
            rub[k] = 2.0f*un - uc;
            ru[k] = un;
        }
        s_rowub[ty*SS + tx] = rub[0];
        if (tx == 32) {
            #pragma unroll
            for (int k = 0; k < PPT; k++) s_seamub[R0 + k] = rub[k];
        }
        __syncthreads();
    }

    if (tx >= KK && tx < KK+TT && gj < 512) {
        #pragma unroll
        for (int k = 0; k < PPT; k++) {
            int r = R0 + k;
            if (r >= KK && r < KK+TT) {
                int gi = gi0 + k;
                if (gi < 512) {
                    size_t go = base + (size_t)gi*512 + gj;
                    if (LAST) {
                        out[go] = fminf(fmaxf(ru[k], 0.0f), 1.0f);
                    } else {
                        g_u [wr][go] = ru[k];
                        g_ub[wr][go] = rub[k];
                        g_px[wr][go] = rpx[k];
                        g_py[wr][go] = rpy[k];
                    }
                }
            }
        }
    }
}

// ---------------- launch (single stream, no device allocations) ----------------
extern "C" void kernel_launch(void* const* d_in, const int* in_sizes, int n_in,
                              void* d_out, int out_size) {
    const float* Iy = (const float*)d_in[0];
    float* out = (float*)d_out;

    const int smbytes = (3*SS*SS + 2*9*SS + 2*SS) * (int)sizeof(float);
    cudaFuncSetAttribute(k_pdshfl<true,false>,  cudaFuncAttributeMaxDynamicSharedMemorySize, smbytes);
    cudaFuncSetAttribute(k_pdshfl<false,false>, cudaFuncAttributeMaxDynamicSharedMemorySize, smbytes);
    cudaFuncSetAttribute(k_pdshfl<false,true>,  cudaFuncAttributeMaxDynamicSharedMemorySize, smbytes);
    const int hist_smx = 4*4096*(int)sizeof(unsigned);   // 64 KB (x, perB=4)
    const int hist_smg = 2*4096*(int)sizeof(unsigned);   // 32 KB (gm, perB=2)
    cudaFuncSetAttribute(k_hist2, cudaFuncAttributeMaxDynamicSharedMemorySize, hist_smx);
    cudaFuncSetAttribute(k_hist3, cudaFuncAttributeMaxDynamicSharedMemorySize, hist_smx);

    dim3 b32x8(32, 8);

    k_zero_hists<<<64, 256>>>();
    k_hpool  <<<dim3(512, NB), 512>>>(Iy);
    k_vpool_x<<<dim3(16, 8, NB), b32x8>>>(Iy);      // + x pass-1 (8-bit)

    // x quantiles: pass-2 (12 bits), pass-3 (12 bits)
    k_hist2<<<dim3(48, NB), 256, hist_smx>>>(0);
    k_hist3<<<dim3(32, NB), 256, hist_smx>>>(0);

    k_nhat<<<dim3(64, NB), 256>>>();                // x-resolve prologue + gm pass-1

    // gm quantiles
    k_hist2<<<dim3(48, NB), 256, hist_smg>>>(1);
    k_hist3<<<dim3(32, NB), 256, hist_smg>>>(1);

    k_wxy<<<dim3(64, NB), 256>>>();                 // gm-resolve prologue

    // 30 PD iterations = 3 fused launches of 10
    dim3 bTile(SS, 8);
    dim3 gTile(NTILE, NTILE, NB);
    k_pdshfl<true,  false><<<gTile, bTile, smbytes>>>(0, 0, nullptr);
    k_pdshfl<false, false><<<gTile, bTile, smbytes>>>(0, 1, nullptr);
    k_pdshfl<false, true ><<<gTile, bTile, smbytes>>>(1, 0, out);
}